// round 1
// baseline (speedup 1.0000x reference)
#include <cuda_runtime.h>
#include <math.h>

#define NN 4096
#define DD 1024
// 1/sqrt(0.07): folded into normalized rows so GEMM directly yields sim/T
#define INV_SQRT_T 3.77964473009227227f

__device__ float g_f[NN * DD];                 // normalized+scaled features (16 MB)
__device__ float g_sim[(size_t)NN * NN];       // similarity matrix (64 MB)
__device__ float g_row[NN];                    // per-row mean_log_prob_pos

// ---------------------------------------------------------------------------
// Kernel 1: L2-normalize each row, multiply by 1/sqrt(T)
// ---------------------------------------------------------------------------
__global__ void __launch_bounds__(256) norm_kernel(const float* __restrict__ x) {
    int row = blockIdx.x;
    int tid = threadIdx.x;
    float4 v = ((const float4*)(x + (size_t)row * DD))[tid];
    float ss = v.x * v.x + v.y * v.y + v.z * v.z + v.w * v.w;
#pragma unroll
    for (int o = 16; o > 0; o >>= 1) ss += __shfl_xor_sync(0xFFFFFFFFu, ss, o);
    __shared__ float wsum[8];
    if ((tid & 31) == 0) wsum[tid >> 5] = ss;
    __syncthreads();
    float tot = 0.f;
#pragma unroll
    for (int w = 0; w < 8; w++) tot += wsum[w];
    float s = INV_SQRT_T / fmaxf(sqrtf(tot), 1e-12f);
    float4 o = make_float4(v.x * s, v.y * s, v.z * s, v.w * s);
    ((float4*)(g_f + (size_t)row * DD))[tid] = o;
}

// ---------------------------------------------------------------------------
// Kernel 2: sim = g_f * g_f^T   (scale already folded in)
// 128x128 block tile, BK=16, 256 threads, 8x8 per thread. Classic SGEMM.
// ---------------------------------------------------------------------------
__global__ void __launch_bounds__(256) gemm_kernel() {
    __shared__ float As[16][128];
    __shared__ float Bs[16][128];
    int bi = blockIdx.y, bj = blockIdx.x;
    int tid = threadIdx.x;
    int tx = tid & 15, ty = tid >> 4;
    int lr = tid >> 2;          // 0..63
    int lk = (tid & 3) << 2;    // 0,4,8,12
    const float* A = g_f + (size_t)bi * 128 * DD;
    const float* B = g_f + (size_t)bj * 128 * DD;

    float acc[8][8];
#pragma unroll
    for (int i = 0; i < 8; i++)
#pragma unroll
        for (int j = 0; j < 8; j++) acc[i][j] = 0.f;

    for (int k0 = 0; k0 < DD; k0 += 16) {
#pragma unroll
        for (int q = 0; q < 2; q++) {
            int r = lr + (q << 6);
            float4 a = *(const float4*)(A + (size_t)r * DD + k0 + lk);
            As[lk + 0][r] = a.x; As[lk + 1][r] = a.y;
            As[lk + 2][r] = a.z; As[lk + 3][r] = a.w;
            float4 b = *(const float4*)(B + (size_t)r * DD + k0 + lk);
            Bs[lk + 0][r] = b.x; Bs[lk + 1][r] = b.y;
            Bs[lk + 2][r] = b.z; Bs[lk + 3][r] = b.w;
        }
        __syncthreads();
#pragma unroll
        for (int k = 0; k < 16; k++) {
            float am[8], bn[8];
            *(float4*)(am)     = *(const float4*)(&As[k][ty * 8]);
            *(float4*)(am + 4) = *(const float4*)(&As[k][ty * 8 + 4]);
            *(float4*)(bn)     = *(const float4*)(&Bs[k][tx * 8]);
            *(float4*)(bn + 4) = *(const float4*)(&Bs[k][tx * 8 + 4]);
#pragma unroll
            for (int i = 0; i < 8; i++)
#pragma unroll
                for (int j = 0; j < 8; j++)
                    acc[i][j] = fmaf(am[i], bn[j], acc[i][j]);
        }
        __syncthreads();
    }
#pragma unroll
    for (int i = 0; i < 8; i++) {
        size_t row = (size_t)(bi * 128 + ty * 8 + i);
        float* C = g_sim + row * NN + bj * 128 + tx * 8;
        *(float4*)C       = make_float4(acc[i][0], acc[i][1], acc[i][2], acc[i][3]);
        *(float4*)(C + 4) = make_float4(acc[i][4], acc[i][5], acc[i][6], acc[i][7]);
    }
}

// ---------------------------------------------------------------------------
// Kernel 3: per-row hard-negative mining + log-prob accumulation.
// One block per row. Exact k-th-largest via 4-pass radix select on
// order-preserving uint keys (non-negatives forced to key 0 = minimum).
// ---------------------------------------------------------------------------
__global__ void __launch_bounds__(256) row_kernel(const int* __restrict__ labels) {
    __shared__ float srow[NN];            // 16 KB
    __shared__ unsigned skey[NN];         // 16 KB
    __shared__ unsigned char sflag[NN];   // 4 KB: 0=neg, 1=pos, 2=self
    __shared__ unsigned hist[256];
    __shared__ unsigned suf[256];
    __shared__ unsigned s_prefix;
    __shared__ int s_k;
    __shared__ float redf[8], redg[8];
    __shared__ int redi[8];

    int i = blockIdx.x;
    int tid = threadIdx.x;
    int lane = tid & 31, wid = tid >> 5;
    int myLabel = labels[i];
    const float* rowp = g_sim + (size_t)i * NN;

    // Load row, build keys/flags, count negatives
    int count = 0;
    for (int j = tid; j < NN; j += 256) {
        float v = rowp[j];
        srow[j] = v;
        int lbl = labels[j];
        bool isNeg = (lbl != myLabel);
        unsigned u = __float_as_uint(v);
        unsigned key = (u & 0x80000000u) ? ~u : (u | 0x80000000u);
        skey[j] = isNeg ? key : 0u;
        sflag[j] = isNeg ? (unsigned char)0 : (j == i ? (unsigned char)2 : (unsigned char)1);
        count += isNeg ? 1 : 0;
    }
#pragma unroll
    for (int o = 16; o > 0; o >>= 1) count += __shfl_xor_sync(0xFFFFFFFFu, count, o);
    if (lane == 0) redi[wid] = count;
    __syncthreads();
    int total = 0;
#pragma unroll
    for (int w = 0; w < 8; w++) total += redi[w];

    if (tid == 0) {
        s_prefix = 0u;
        int k = total >> 1;            // floor(count * 0.5)
        s_k = k < 1 ? 1 : k;
    }
    __syncthreads();

    // 4-pass radix select (MSB first), warp-aggregated histogram atomics
#pragma unroll
    for (int pass = 0; pass < 4; pass++) {
        int shift = 24 - pass * 8;
        unsigned mask = ~(0xFFFFFFFFu >> (8 * pass));   // pass0 -> 0
        hist[tid] = 0;
        __syncthreads();
        unsigned prefVal = s_prefix;
        int k = s_k;
        for (int j = tid; j < NN; j += 256) {
            unsigned key = skey[j];
            bool match = ((key & mask) == prefVal);
            unsigned bin = (key >> shift) & 255u;
            unsigned active = __ballot_sync(0xFFFFFFFFu, match);
            if (match) {
                unsigned peers = __match_any_sync(active, bin);
                int leader = __ffs(peers) - 1;
                if (lane == leader) atomicAdd(&hist[bin], (unsigned)__popc(peers));
            }
        }
        __syncthreads();
        unsigned h = hist[tid];
        suf[tid] = h;
        __syncthreads();
#pragma unroll
        for (int off = 1; off < 256; off <<= 1) {
            unsigned add = (tid + off < 256) ? suf[tid + off] : 0u;
            __syncthreads();
            suf[tid] += add;
            __syncthreads();
        }
        unsigned sb = suf[tid];
        unsigned snext = (tid < 255) ? suf[tid + 1] : 0u;
        if ((int)sb >= k && (int)snext < k) {       // exactly one thread
            s_prefix = prefVal | ((unsigned)tid << shift);
            s_k = k - (int)snext;
        }
        __syncthreads();
    }

    // threshold key -> float (inverse of the order-preserving map)
    unsigned tk = s_prefix;
    unsigned tu = (tk & 0x80000000u) ? (tk & 0x7FFFFFFFu) : ~tk;
    float thr = __uint_as_float(tu);

    // Final pass: denominator and positive sums
    float negExp = 0.f, posSum = 0.f;
    int posCnt = 0;
    for (int j = tid; j < NN; j += 256) {
        float v = srow[j];
        unsigned char f = sflag[j];
        if (f == 0) {
            if (v >= thr) negExp += expf(v);
        } else if (f == 1) {
            posSum += v;
            posCnt++;
        }
    }
#pragma unroll
    for (int o = 16; o > 0; o >>= 1) {
        negExp += __shfl_xor_sync(0xFFFFFFFFu, negExp, o);
        posSum += __shfl_xor_sync(0xFFFFFFFFu, posSum, o);
        posCnt += __shfl_xor_sync(0xFFFFFFFFu, posCnt, o);
    }
    if (lane == 0) { redf[wid] = negExp; redg[wid] = posSum; redi[wid] = posCnt; }
    __syncthreads();
    if (tid == 0) {
        float ne = 0.f, ps = 0.f; int pc = 0;
#pragma unroll
        for (int w = 0; w < 8; w++) { ne += redf[w]; ps += redg[w]; pc += redi[w]; }
        float selfE = expf(srow[i]);
        float denom = ne + selfE + 1e-10f;
        float pcf = (float)pc;
        g_row[i] = (ps - pcf * logf(denom)) / (pcf + 1e-10f);
    }
}

// ---------------------------------------------------------------------------
// Kernel 4: deterministic final reduction -> scalar loss
// ---------------------------------------------------------------------------
__global__ void __launch_bounds__(256) reduce_kernel(float* __restrict__ out) {
    int tid = threadIdx.x;
    float s = 0.f;
    for (int j = tid; j < NN; j += 256) s += g_row[j];
#pragma unroll
    for (int o = 16; o > 0; o >>= 1) s += __shfl_xor_sync(0xFFFFFFFFu, s, o);
    __shared__ float red[8];
    if ((tid & 31) == 0) red[tid >> 5] = s;
    __syncthreads();
    if (tid == 0) {
        float t = 0.f;
#pragma unroll
        for (int w = 0; w < 8; w++) t += red[w];
        out[0] = -t / (float)NN;
    }
}

extern "C" void kernel_launch(void* const* d_in, const int* in_sizes, int n_in,
                              void* d_out, int out_size) {
    const float* features = (const float*)d_in[0];
    const int*   labels   = (const int*)d_in[1];
    norm_kernel<<<NN, 256>>>(features);
    gemm_kernel<<<dim3(32, 32), 256>>>();
    row_kernel<<<NN, 256>>>(labels);
    reduce_kernel<<<1, 256>>>((float*)d_out);
}

// round 3
// speedup vs baseline: 2.5479x; 2.5479x over previous
#include <cuda_runtime.h>
#include <math.h>
#include <stdint.h>

#define NN 4096
#define DD 1024
// 1/sqrt(0.07): folded into normalized rows so GEMM directly yields sim/T
#define INV_SQRT_T 3.77964473009227227f

__device__ float g_f[NN * DD];                 // normalized+scaled+tf32-rounded features
__device__ float g_sim[(size_t)NN * NN];       // similarity matrix (64 MB)
__device__ float g_row[NN];                    // per-row mean_log_prob_pos

// ---------------------------------------------------------------------------
// Kernel 1: L2-normalize each row, multiply by 1/sqrt(T), round to tf32
// ---------------------------------------------------------------------------
__global__ void __launch_bounds__(256) norm_kernel(const float* __restrict__ x) {
    int row = blockIdx.x;
    int tid = threadIdx.x;
    float4 v = ((const float4*)(x + (size_t)row * DD))[tid];
    float ss = v.x * v.x + v.y * v.y + v.z * v.z + v.w * v.w;
#pragma unroll
    for (int o = 16; o > 0; o >>= 1) ss += __shfl_xor_sync(0xFFFFFFFFu, ss, o);
    __shared__ float wsum[8];
    if ((tid & 31) == 0) wsum[tid >> 5] = ss;
    __syncthreads();
    float tot = 0.f;
#pragma unroll
    for (int w = 0; w < 8; w++) tot += wsum[w];
    float s = INV_SQRT_T / fmaxf(sqrtf(tot), 1e-12f);
    float4 o = make_float4(v.x * s, v.y * s, v.z * s, v.w * s);
    // round-to-nearest tf32 so the mma's truncation is exact
    asm("cvt.rna.tf32.f32 %0, %0;" : "+f"(o.x));
    asm("cvt.rna.tf32.f32 %0, %0;" : "+f"(o.y));
    asm("cvt.rna.tf32.f32 %0, %0;" : "+f"(o.z));
    asm("cvt.rna.tf32.f32 %0, %0;" : "+f"(o.w));
    ((float4*)(g_f + (size_t)row * DD))[tid] = o;
}

// ---------------------------------------------------------------------------
// Kernel 2: sim = g_f * g_f^T via mma.sync tf32 (m16n8k8), cp.async pipeline
// 128x128 CTA tile, BK=32, 8 warps (2x4), 64x32 warp tile.
// Smem rows padded to 36 floats: 144B row stride keeps cp.async 16B-aligned
// and makes fragment lds conflict-free.
// ---------------------------------------------------------------------------
#define BK 32
#define LDR 36                              /* padded row length in floats */
#define TILE_F (128 * LDR)                  /* floats per operand tile */
#define STAGE_F (2 * TILE_F)                /* A + B per stage */
#define GEMM_SMEM (2 * STAGE_F * 4)         /* bytes, double buffered: 73728 */

__global__ void __launch_bounds__(256) gemm_mma() {
    extern __shared__ float smem[];
    float* As[2] = { smem,                smem + STAGE_F };
    float* Bs[2] = { smem + TILE_F,       smem + STAGE_F + TILE_F };

    int tid = threadIdx.x, wid = tid >> 5, lane = tid & 31;
    int warpM = wid >> 2, warpN = wid & 3;   // 2 x 4
    int bi = blockIdx.y, bj = blockIdx.x;
    const float* Abase = g_f + (size_t)bi * 128 * DD;
    const float* Bbase = g_f + (size_t)bj * 128 * DD;

    float acc[4][4][4];
#pragma unroll
    for (int m = 0; m < 4; m++)
#pragma unroll
        for (int n = 0; n < 4; n++)
#pragma unroll
            for (int q = 0; q < 4; q++) acc[m][n][q] = 0.f;

    auto load_chunk = [&](int ch, int s) {
#pragma unroll
        for (int r = 0; r < 4; r++) {
            int c = tid + r * 256;            // 0..1023
            int row = c >> 3;                 // 0..127
            int k4 = (c & 7) << 2;            // 0,4,...,28
            uint32_t dA, dB;
            asm("{ .reg .u64 t; cvta.to.shared.u64 t, %1; cvt.u32.u64 %0, t; }"
                : "=r"(dA) : "l"(As[s] + row * LDR + k4));
            asm("{ .reg .u64 t; cvta.to.shared.u64 t, %1; cvt.u32.u64 %0, t; }"
                : "=r"(dB) : "l"(Bs[s] + row * LDR + k4));
            unsigned long long sA = (unsigned long long)__cvta_generic_to_global(
                Abase + (size_t)row * DD + ch * BK + k4);
            unsigned long long sB = (unsigned long long)__cvta_generic_to_global(
                Bbase + (size_t)row * DD + ch * BK + k4);
            asm volatile("cp.async.cg.shared.global [%0], [%1], 16;" :: "r"(dA), "l"(sA));
            asm volatile("cp.async.cg.shared.global [%0], [%1], 16;" :: "r"(dB), "l"(sB));
        }
        asm volatile("cp.async.commit_group;" ::: "memory");
    };

    const int NKCH = DD / BK;                // 32
    load_chunk(0, 0);

    for (int ch = 0; ch < NKCH; ch++) {
        int s = ch & 1;
        if (ch + 1 < NKCH) {
            load_chunk(ch + 1, s ^ 1);
            asm volatile("cp.async.wait_group 1;" ::: "memory");
        } else {
            asm volatile("cp.async.wait_group 0;" ::: "memory");
        }
        __syncthreads();

        const float* Asm = As[s];
        const float* Bsm = Bs[s];
#pragma unroll
        for (int k0 = 0; k0 < 4; k0++) {     // 4 k-steps of 8
            int kk = k0 * 8 + (lane & 3);
            uint32_t a[4][4], b[4][2];
#pragma unroll
            for (int m = 0; m < 4; m++) {
                int row = warpM * 64 + m * 16 + (lane >> 2);
                a[m][0] = __float_as_uint(Asm[row * LDR + kk]);
                a[m][1] = __float_as_uint(Asm[(row + 8) * LDR + kk]);
                a[m][2] = __float_as_uint(Asm[row * LDR + kk + 4]);
                a[m][3] = __float_as_uint(Asm[(row + 8) * LDR + kk + 4]);
            }
#pragma unroll
            for (int n = 0; n < 4; n++) {
                int col = warpN * 32 + n * 8 + (lane >> 2);
                b[n][0] = __float_as_uint(Bsm[col * LDR + kk]);
                b[n][1] = __float_as_uint(Bsm[col * LDR + kk + 4]);
            }
#pragma unroll
            for (int m = 0; m < 4; m++)
#pragma unroll
                for (int n = 0; n < 4; n++)
                    asm volatile(
                        "mma.sync.aligned.m16n8k8.row.col.f32.tf32.tf32.f32 "
                        "{%0,%1,%2,%3}, {%4,%5,%6,%7}, {%8,%9}, {%0,%1,%2,%3};"
                        : "+f"(acc[m][n][0]), "+f"(acc[m][n][1]),
                          "+f"(acc[m][n][2]), "+f"(acc[m][n][3])
                        : "r"(a[m][0]), "r"(a[m][1]), "r"(a[m][2]), "r"(a[m][3]),
                          "r"(b[n][0]), "r"(b[n][1]));
        }
        __syncthreads();
    }

    // Epilogue: c0/c1 at (row, col..col+1), c2/c3 at (row+8, ...)
#pragma unroll
    for (int m = 0; m < 4; m++) {
        size_t row0 = (size_t)(bi * 128 + warpM * 64 + m * 16 + (lane >> 2));
#pragma unroll
        for (int n = 0; n < 4; n++) {
            int col = bj * 128 + warpN * 32 + n * 8 + (lane & 3) * 2;
            *(float2*)(g_sim + row0 * NN + col) = make_float2(acc[m][n][0], acc[m][n][1]);
            *(float2*)(g_sim + (row0 + 8) * NN + col) = make_float2(acc[m][n][2], acc[m][n][3]);
        }
    }
}

// ---------------------------------------------------------------------------
// Kernel 3: per-row hard-negative mining + log-prob accumulation.
// One block per row. Exact k-th-largest via 4-pass radix select.
// ---------------------------------------------------------------------------
__global__ void __launch_bounds__(256) row_kernel(const int* __restrict__ labels) {
    __shared__ float srow[NN];
    __shared__ unsigned skey[NN];
    __shared__ unsigned char sflag[NN];
    __shared__ unsigned hist[256];
    __shared__ unsigned suf[256];
    __shared__ unsigned s_prefix;
    __shared__ int s_k;
    __shared__ float redf[8], redg[8];
    __shared__ int redi[8];

    int i = blockIdx.x;
    int tid = threadIdx.x;
    int lane = tid & 31, wid = tid >> 5;
    int myLabel = labels[i];
    const float* rowp = g_sim + (size_t)i * NN;

    int count = 0;
    for (int j = tid; j < NN; j += 256) {
        float v = rowp[j];
        srow[j] = v;
        int lbl = labels[j];
        bool isNeg = (lbl != myLabel);
        unsigned u = __float_as_uint(v);
        unsigned key = (u & 0x80000000u) ? ~u : (u | 0x80000000u);
        skey[j] = isNeg ? key : 0u;
        sflag[j] = isNeg ? (unsigned char)0 : (j == i ? (unsigned char)2 : (unsigned char)1);
        count += isNeg ? 1 : 0;
    }
#pragma unroll
    for (int o = 16; o > 0; o >>= 1) count += __shfl_xor_sync(0xFFFFFFFFu, count, o);
    if (lane == 0) redi[wid] = count;
    __syncthreads();
    int total = 0;
#pragma unroll
    for (int w = 0; w < 8; w++) total += redi[w];

    if (tid == 0) {
        s_prefix = 0u;
        int k = total >> 1;
        s_k = k < 1 ? 1 : k;
    }
    __syncthreads();

#pragma unroll
    for (int pass = 0; pass < 4; pass++) {
        int shift = 24 - pass * 8;
        unsigned mask = ~(0xFFFFFFFFu >> (8 * pass));
        hist[tid] = 0;
        __syncthreads();
        unsigned prefVal = s_prefix;
        int k = s_k;
        for (int j = tid; j < NN; j += 256) {
            unsigned key = skey[j];
            bool match = ((key & mask) == prefVal);
            unsigned bin = (key >> shift) & 255u;
            unsigned active = __ballot_sync(0xFFFFFFFFu, match);
            if (match) {
                unsigned peers = __match_any_sync(active, bin);
                int leader = __ffs(peers) - 1;
                if (lane == leader) atomicAdd(&hist[bin], (unsigned)__popc(peers));
            }
        }
        __syncthreads();
        unsigned h = hist[tid];
        suf[tid] = h;
        __syncthreads();
#pragma unroll
        for (int off = 1; off < 256; off <<= 1) {
            unsigned add = (tid + off < 256) ? suf[tid + off] : 0u;
            __syncthreads();
            suf[tid] += add;
            __syncthreads();
        }
        unsigned sb2 = suf[tid];
        unsigned snext = (tid < 255) ? suf[tid + 1] : 0u;
        if ((int)sb2 >= k && (int)snext < k) {
            s_prefix = prefVal | ((unsigned)tid << shift);
            s_k = k - (int)snext;
        }
        __syncthreads();
    }

    unsigned tk = s_prefix;
    unsigned tu = (tk & 0x80000000u) ? (tk & 0x7FFFFFFFu) : ~tk;
    float thr = __uint_as_float(tu);

    float negExp = 0.f, posSum = 0.f;
    int posCnt = 0;
    for (int j = tid; j < NN; j += 256) {
        float v = srow[j];
        unsigned char f = sflag[j];
        if (f == 0) {
            if (v >= thr) negExp += expf(v);
        } else if (f == 1) {
            posSum += v;
            posCnt++;
        }
    }
#pragma unroll
    for (int o = 16; o > 0; o >>= 1) {
        negExp += __shfl_xor_sync(0xFFFFFFFFu, negExp, o);
        posSum += __shfl_xor_sync(0xFFFFFFFFu, posSum, o);
        posCnt += __shfl_xor_sync(0xFFFFFFFFu, posCnt, o);
    }
    if (lane == 0) { redf[wid] = negExp; redg[wid] = posSum; redi[wid] = posCnt; }
    __syncthreads();
    if (tid == 0) {
        float ne = 0.f, ps = 0.f; int pc = 0;
#pragma unroll
        for (int w = 0; w < 8; w++) { ne += redf[w]; ps += redg[w]; pc += redi[w]; }
        float selfE = expf(srow[i]);
        float denom = ne + selfE + 1e-10f;
        float pcf = (float)pc;
        g_row[i] = (ps - pcf * logf(denom)) / (pcf + 1e-10f);
    }
}

// ---------------------------------------------------------------------------
// Kernel 4: deterministic final reduction -> scalar loss
// ---------------------------------------------------------------------------
__global__ void __launch_bounds__(256) reduce_kernel(float* __restrict__ out) {
    int tid = threadIdx.x;
    float s = 0.f;
    for (int j = tid; j < NN; j += 256) s += g_row[j];
#pragma unroll
    for (int o = 16; o > 0; o >>= 1) s += __shfl_xor_sync(0xFFFFFFFFu, s, o);
    __shared__ float red[8];
    if ((tid & 31) == 0) red[tid >> 5] = s;
    __syncthreads();
    if (tid == 0) {
        float t = 0.f;
#pragma unroll
        for (int w = 0; w < 8; w++) t += red[w];
        out[0] = -t / (float)NN;
    }
}

extern "C" void kernel_launch(void* const* d_in, const int* in_sizes, int n_in,
                              void* d_out, int out_size) {
    const float* features = (const float*)d_in[0];
    const int*   labels   = (const int*)d_in[1];
    static bool attr_set = false;
    if (!attr_set) {
        cudaFuncSetAttribute(gemm_mma, cudaFuncAttributeMaxDynamicSharedMemorySize, GEMM_SMEM);
        attr_set = true;
    }
    norm_kernel<<<NN, 256>>>(features);
    gemm_mma<<<dim3(32, 32), 256, GEMM_SMEM>>>();
    row_kernel<<<NN, 256>>>(labels);
    reduce_kernel<<<1, 256>>>((float*)d_out);
}

// round 4
// speedup vs baseline: 3.7937x; 1.4890x over previous
#include <cuda_runtime.h>
#include <math.h>
#include <stdint.h>

#define NN 4096
#define DD 1024
// 1/sqrt(0.07): folded into normalized rows so GEMM directly yields sim/T
#define INV_SQRT_T 3.77964473009227227f
#define FIXSCALE 17179869184.0f   /* 2^34 */

__device__ float g_f[NN * DD];                 // normalized+scaled+tf32-rounded features
__device__ float g_sim[(size_t)NN * NN];       // similarity matrix (64 MB)
__device__ unsigned long long g_accum;         // fixed-point loss accumulator
__device__ unsigned int g_done;                // completed-row counter

// ---------------------------------------------------------------------------
// Kernel 1: L2-normalize each row, multiply by 1/sqrt(T), round to tf32.
// Block 0 also resets the global accumulators (runs before row_kernel).
// ---------------------------------------------------------------------------
__global__ void __launch_bounds__(256) norm_kernel(const float* __restrict__ x) {
    int row = blockIdx.x;
    int tid = threadIdx.x;
    if (row == 0 && tid == 0) { g_accum = 0ULL; g_done = 0u; }
    float4 v = ((const float4*)(x + (size_t)row * DD))[tid];
    float ss = v.x * v.x + v.y * v.y + v.z * v.z + v.w * v.w;
#pragma unroll
    for (int o = 16; o > 0; o >>= 1) ss += __shfl_xor_sync(0xFFFFFFFFu, ss, o);
    __shared__ float wsum[8];
    if ((tid & 31) == 0) wsum[tid >> 5] = ss;
    __syncthreads();
    float tot = 0.f;
#pragma unroll
    for (int w = 0; w < 8; w++) tot += wsum[w];
    float s = INV_SQRT_T / fmaxf(sqrtf(tot), 1e-12f);
    float4 o = make_float4(v.x * s, v.y * s, v.z * s, v.w * s);
    asm("cvt.rna.tf32.f32 %0, %0;" : "+f"(o.x));
    asm("cvt.rna.tf32.f32 %0, %0;" : "+f"(o.y));
    asm("cvt.rna.tf32.f32 %0, %0;" : "+f"(o.z));
    asm("cvt.rna.tf32.f32 %0, %0;" : "+f"(o.w));
    ((float4*)(g_f + (size_t)row * DD))[tid] = o;
}

// ---------------------------------------------------------------------------
// Kernel 2: sim = g_f * g_f^T via mma.sync tf32 (m16n8k8), cp.async pipeline.
// SYMMETRIC: only the 528 upper-triangle 128x128 tiles are computed; each
// off-diagonal tile is stored twice (direct + transposed).
// ---------------------------------------------------------------------------
#define BK 32
#define LDR 36                              /* padded row length in floats */
#define TILE_F (128 * LDR)
#define STAGE_F (2 * TILE_F)
#define GEMM_SMEM (2 * STAGE_F * 4)         /* 73728 bytes */
#define NTILE 32
#define NBLK (NTILE * (NTILE + 1) / 2)      /* 528 */

__global__ void __launch_bounds__(256) gemm_mma() {
    extern __shared__ float smem[];
    float* As[2] = { smem,          smem + STAGE_F };
    float* Bs[2] = { smem + TILE_F, smem + STAGE_F + TILE_F };

    int tid = threadIdx.x, wid = tid >> 5, lane = tid & 31;
    int warpM = wid >> 2, warpN = wid & 3;   // 2 x 4

    // decode upper-triangle tile index -> (bi, bj), bi <= bj
    int idx = blockIdx.x;
    int bi = (int)((65.0 - sqrt((double)(4225 - 8 * idx))) * 0.5);
    if (bi < 0) bi = 0;
    if (bi > 31) bi = 31;
#define TRI_OFF(b) ((b) * 32 - ((b) * ((b) - 1)) / 2)
    while (bi < 31 && TRI_OFF(bi + 1) <= idx) bi++;
    while (bi > 0 && TRI_OFF(bi) > idx) bi--;
    int bj = bi + (idx - TRI_OFF(bi));

    const float* Abase = g_f + (size_t)bi * 128 * DD;
    const float* Bbase = g_f + (size_t)bj * 128 * DD;

    float acc[4][4][4];
#pragma unroll
    for (int m = 0; m < 4; m++)
#pragma unroll
        for (int n = 0; n < 4; n++)
#pragma unroll
            for (int q = 0; q < 4; q++) acc[m][n][q] = 0.f;

    auto load_chunk = [&](int ch, int s) {
#pragma unroll
        for (int r = 0; r < 4; r++) {
            int c = tid + r * 256;
            int row = c >> 3;
            int k4 = (c & 7) << 2;
            uint32_t dA, dB;
            asm("{ .reg .u64 t; cvta.to.shared.u64 t, %1; cvt.u32.u64 %0, t; }"
                : "=r"(dA) : "l"(As[s] + row * LDR + k4));
            asm("{ .reg .u64 t; cvta.to.shared.u64 t, %1; cvt.u32.u64 %0, t; }"
                : "=r"(dB) : "l"(Bs[s] + row * LDR + k4));
            unsigned long long sA = (unsigned long long)__cvta_generic_to_global(
                Abase + (size_t)row * DD + ch * BK + k4);
            unsigned long long sB = (unsigned long long)__cvta_generic_to_global(
                Bbase + (size_t)row * DD + ch * BK + k4);
            asm volatile("cp.async.cg.shared.global [%0], [%1], 16;" :: "r"(dA), "l"(sA));
            asm volatile("cp.async.cg.shared.global [%0], [%1], 16;" :: "r"(dB), "l"(sB));
        }
        asm volatile("cp.async.commit_group;" ::: "memory");
    };

    const int NKCH = DD / BK;                // 32
    load_chunk(0, 0);

    for (int ch = 0; ch < NKCH; ch++) {
        int s = ch & 1;
        if (ch + 1 < NKCH) {
            load_chunk(ch + 1, s ^ 1);
            asm volatile("cp.async.wait_group 1;" ::: "memory");
        } else {
            asm volatile("cp.async.wait_group 0;" ::: "memory");
        }
        __syncthreads();

        const float* Asm = As[s];
        const float* Bsm = Bs[s];
#pragma unroll
        for (int k0 = 0; k0 < 4; k0++) {
            int kk = k0 * 8 + (lane & 3);
            uint32_t a[4][4], b[4][2];
#pragma unroll
            for (int m = 0; m < 4; m++) {
                int row = warpM * 64 + m * 16 + (lane >> 2);
                a[m][0] = __float_as_uint(Asm[row * LDR + kk]);
                a[m][1] = __float_as_uint(Asm[(row + 8) * LDR + kk]);
                a[m][2] = __float_as_uint(Asm[row * LDR + kk + 4]);
                a[m][3] = __float_as_uint(Asm[(row + 8) * LDR + kk + 4]);
            }
#pragma unroll
            for (int n = 0; n < 4; n++) {
                int col = warpN * 32 + n * 8 + (lane >> 2);
                b[n][0] = __float_as_uint(Bsm[col * LDR + kk]);
                b[n][1] = __float_as_uint(Bsm[col * LDR + kk + 4]);
            }
#pragma unroll
            for (int m = 0; m < 4; m++)
#pragma unroll
                for (int n = 0; n < 4; n++)
                    asm volatile(
                        "mma.sync.aligned.m16n8k8.row.col.f32.tf32.tf32.f32 "
                        "{%0,%1,%2,%3}, {%4,%5,%6,%7}, {%8,%9}, {%0,%1,%2,%3};"
                        : "+f"(acc[m][n][0]), "+f"(acc[m][n][1]),
                          "+f"(acc[m][n][2]), "+f"(acc[m][n][3])
                        : "r"(a[m][0]), "r"(a[m][1]), "r"(a[m][2]), "r"(a[m][3]),
                          "r"(b[n][0]), "r"(b[n][1]));
        }
        __syncthreads();
    }

    // Epilogue: direct tile
#pragma unroll
    for (int m = 0; m < 4; m++) {
        size_t row0 = (size_t)(bi * 128 + warpM * 64 + m * 16 + (lane >> 2));
#pragma unroll
        for (int n = 0; n < 4; n++) {
            int col = bj * 128 + warpN * 32 + n * 8 + (lane & 3) * 2;
            *(float2*)(g_sim + row0 * NN + col) = make_float2(acc[m][n][0], acc[m][n][1]);
            *(float2*)(g_sim + (row0 + 8) * NN + col) = make_float2(acc[m][n][2], acc[m][n][3]);
        }
    }
    // Transposed tile (off-diagonal only)
    if (bi != bj) {
#pragma unroll
        for (int m = 0; m < 4; m++) {
            int r0 = bi * 128 + warpM * 64 + m * 16 + (lane >> 2);
#pragma unroll
            for (int n = 0; n < 4; n++) {
                int c0 = bj * 128 + warpN * 32 + n * 8 + (lane & 3) * 2;
                g_sim[(size_t)c0 * NN + r0]           = acc[m][n][0];
                g_sim[(size_t)(c0 + 1) * NN + r0]     = acc[m][n][1];
                g_sim[(size_t)c0 * NN + r0 + 8]       = acc[m][n][2];
                g_sim[(size_t)(c0 + 1) * NN + r0 + 8] = acc[m][n][3];
            }
        }
    }
}

// ---------------------------------------------------------------------------
// warp-0 suffix-scan + bucket select over a 256-bin histogram
// ---------------------------------------------------------------------------
__device__ __forceinline__ void warp_scan_select(
    const unsigned* hist, unsigned prefVal, int shift, int k,
    unsigned* s_prefix, int* s_k) {
    int lane = threadIdx.x & 31;
    int base = lane * 8;
    unsigned h[8]; unsigned t = 0;
#pragma unroll
    for (int q = 0; q < 8; q++) { h[q] = hist[base + q]; t += h[q]; }
    unsigned ssum = t;
#pragma unroll
    for (int off = 1; off < 32; off <<= 1) {
        unsigned tmp = __shfl_down_sync(0xFFFFFFFFu, ssum, off);
        if (lane + off < 32) ssum += tmp;
    }
    unsigned above = ssum - t;           // sum over bins owned by higher lanes
    unsigned sufv[8]; unsigned run = above;
#pragma unroll
    for (int q = 7; q >= 0; q--) { run += h[q]; sufv[q] = run; }
    __syncwarp();
#pragma unroll
    for (int q = 0; q < 8; q++) {
        unsigned sb = sufv[q];
        unsigned sn = (q < 7) ? sufv[q + 1] : above;
        if ((int)sb >= k && (int)sn < k) {
            *s_prefix = prefVal | ((unsigned)(base + q) << (unsigned)shift);
            *s_k = k - (int)sn;
        }
    }
}

// ---------------------------------------------------------------------------
// Kernel 3: per-row hard-negative mining + log-prob + fixed-point global sum.
// ---------------------------------------------------------------------------
__global__ void __launch_bounds__(256) row_kernel(const int* __restrict__ labels,
                                                  float* __restrict__ out) {
    __shared__ float srow[NN];
    __shared__ unsigned skey[NN];
    __shared__ unsigned char sflag[NN];
    __shared__ unsigned hist[256];
    __shared__ unsigned s_prefix;
    __shared__ int s_k;
    __shared__ float redf[8], redg[8];
    __shared__ int redi[8];

    int i = blockIdx.x;
    int tid = threadIdx.x;
    int lane = tid & 31, wid = tid >> 5;
    int myLabel = labels[i];
    const float* rowp = g_sim + (size_t)i * NN;

    hist[tid] = 0;
    __syncthreads();

    // Load sweep: build srow/skey/sflag, count negatives, pass-0 histogram
    int count = 0;
    for (int j = tid; j < NN; j += 256) {
        float v = rowp[j];
        srow[j] = v;
        int lbl = labels[j];
        bool isNeg = (lbl != myLabel);
        unsigned u = __float_as_uint(v);
        unsigned key = (u & 0x80000000u) ? ~u : (u | 0x80000000u);
        key = isNeg ? key : 0u;
        skey[j] = key;
        sflag[j] = isNeg ? (unsigned char)0 : (j == i ? (unsigned char)2 : (unsigned char)1);
        count += isNeg ? 1 : 0;
        unsigned bin = key >> 24;
        unsigned peers = __match_any_sync(0xFFFFFFFFu, bin);
        if ((__ffs(peers) - 1) == lane) atomicAdd(&hist[bin], (unsigned)__popc(peers));
    }
#pragma unroll
    for (int o = 16; o > 0; o >>= 1) count += __shfl_xor_sync(0xFFFFFFFFu, count, o);
    if (lane == 0) redi[wid] = count;
    __syncthreads();

    // Pass 0 scan (warp 0)
    if (wid == 0) {
        int total = 0;
#pragma unroll
        for (int w = 0; w < 8; w++) total += redi[w];
        int k0 = total >> 1;
        if (k0 < 1) k0 = 1;
        warp_scan_select(hist, 0u, 24, k0, &s_prefix, &s_k);
    }
    __syncthreads();

    // Passes 1..3
#pragma unroll
    for (int pass = 1; pass < 4; pass++) {
        int shift = 24 - pass * 8;
        unsigned mask = ~(0xFFFFFFFFu >> (8 * pass));
        hist[tid] = 0;
        __syncthreads();
        unsigned prefVal = s_prefix;
        for (int j = tid; j < NN; j += 256) {
            unsigned key = skey[j];
            bool match = ((key & mask) == prefVal);
            unsigned bin = (key >> shift) & 255u;
            unsigned active = __ballot_sync(0xFFFFFFFFu, match);
            if (match) {
                unsigned peers = __match_any_sync(active, bin);
                if ((__ffs(peers) - 1) == lane) atomicAdd(&hist[bin], (unsigned)__popc(peers));
            }
        }
        __syncthreads();
        if (wid == 0) warp_scan_select(hist, prefVal, shift, s_k, &s_prefix, &s_k);
        __syncthreads();
    }

    // threshold key -> float
    unsigned tk = s_prefix;
    unsigned tu = (tk & 0x80000000u) ? (tk & 0x7FFFFFFFu) : ~tk;
    float thr = __uint_as_float(tu);

    // Final sweep
    float negExp = 0.f, posSum = 0.f;
    int posCnt = 0;
    for (int j = tid; j < NN; j += 256) {
        float v = srow[j];
        unsigned char f = sflag[j];
        if (f == 0) {
            if (v >= thr) negExp += expf(v);
        } else if (f == 1) {
            posSum += v;
            posCnt++;
        }
    }
#pragma unroll
    for (int o = 16; o > 0; o >>= 1) {
        negExp += __shfl_xor_sync(0xFFFFFFFFu, negExp, o);
        posSum += __shfl_xor_sync(0xFFFFFFFFu, posSum, o);
        posCnt += __shfl_xor_sync(0xFFFFFFFFu, posCnt, o);
    }
    if (lane == 0) { redf[wid] = negExp; redg[wid] = posSum; redi[wid] = posCnt; }
    __syncthreads();
    if (tid == 0) {
        float ne = 0.f, ps = 0.f; int pc = 0;
#pragma unroll
        for (int w = 0; w < 8; w++) { ne += redf[w]; ps += redg[w]; pc += redi[w]; }
        float selfE = expf(srow[i]);
        float denom = ne + selfE + 1e-10f;
        float pcf = (float)pc;
        float val = (ps - pcf * logf(denom)) / (pcf + 1e-10f);
        // deterministic fixed-point accumulation (2^34 scale)
        long long fx = __float2ll_rn(val * FIXSCALE);
        atomicAdd(&g_accum, (unsigned long long)fx);
        __threadfence();
        unsigned prev = atomicAdd(&g_done, 1u);
        if (prev == NN - 1) {
            unsigned long long acc = atomicAdd(&g_accum, 0ULL);
            double sum = (double)(long long)acc;
            out[0] = (float)(-sum / ((double)FIXSCALE * (double)NN));
        }
    }
}

extern "C" void kernel_launch(void* const* d_in, const int* in_sizes, int n_in,
                              void* d_out, int out_size) {
    const float* features = (const float*)d_in[0];
    const int*   labels   = (const int*)d_in[1];
    cudaFuncSetAttribute(gemm_mma, cudaFuncAttributeMaxDynamicSharedMemorySize, GEMM_SMEM);
    norm_kernel<<<NN, 256>>>(features);
    gemm_mma<<<NBLK, 256, GEMM_SMEM>>>();
    row_kernel<<<NN, 256>>>(labels, (float*)d_out);
}